// round 5
// baseline (speedup 1.0000x reference)
#include <cuda_runtime.h>

// NeuralFSM == discrete automaton (exact):
//   state[n] in {0..7}; per iter mask[n] = OR of (1<<state[j]) over in-neighbors;
//   state'[n] = table[mask[n]][state[n]].
// Round 5: degree-sorted slot permutation (counting sort, once) so warps have
// uniform trip counts; ELL adjacency in slot space (coalesced); grid covers all
// 148 SMs with round-robin warp->degree mapping; 4-wide unrolled gathers with
// sentinel padding (branch-free inner loop).

#define MAXN 100000
#define NST  8
#define ELLW 192                       // max in-degree bound (Poisson(64): max ~110)
#define NBIN 256

__device__ __align__(16) unsigned char g_stA[MAXN];       // state, slot space
__device__ __align__(16) unsigned char g_stB[MAXN];
__device__ __align__(16) unsigned char g_sbA[MAXN + 16];  // 1<<state, NODE space (+sentinel)
__device__ __align__(16) unsigned char g_sbB[MAXN + 16];
__device__ unsigned char g_table[256 * NST];
__device__ unsigned int  g_deg[MAXN];          // in-degree per node
__device__ unsigned int  g_rank[MAXN];         // node -> slot
__device__ int           g_nodeofslot[MAXN];   // slot -> node
__device__ unsigned int  g_degslot[MAXN];      // degree per slot
__device__ unsigned int  g_cur[MAXN];          // scatter cursor per slot
__device__ unsigned int  g_bins[NBIN];
__device__ unsigned int  g_bincur[NBIN];
__device__ int           g_ell[(size_t)ELLW * MAXN];  // ell[j*MAXN + slot] = src node id

static __device__ __forceinline__ int onehot_idx(float4 a, float4 b) {
    int st = 0;
    if (a.y > 0.5f) st = 1;
    if (a.z > 0.5f) st = 2;
    if (a.w > 0.5f) st = 3;
    if (b.x > 0.5f) st = 4;
    if (b.y > 0.5f) st = 5;
    if (b.z > 0.5f) st = 6;
    if (b.w > 0.5f) st = 7;
    return st;
}

__global__ void k_zero(int n) {
    int i = blockIdx.x * blockDim.x + threadIdx.x;
    if (i < n) g_deg[i] = 0u;
    if (i < NBIN) g_bins[i] = 0u;
}

__global__ void k_table(const float* __restrict__ T) {
    int i = blockIdx.x * blockDim.x + threadIdx.x;
    if (i >= 256 * NST) return;
    const float4* p = (const float4*)(T + (size_t)i * 8);
    g_table[i] = (unsigned char)onehot_idx(p[0], p[1]);
}

// In-degree histogram.
__global__ void k_hist(const int* __restrict__ dst, int E) {
    int tid = blockIdx.x * blockDim.x + threadIdx.x;
    int stride = gridDim.x * blockDim.x;
    int nv = E >> 2;
    const int4* d4p = (const int4*)dst;
    for (int v = tid; v < nv; v += stride) {
        int4 d = __ldg(&d4p[v]);
        atomicAdd(&g_deg[d.x], 1u);
        atomicAdd(&g_deg[d.y], 1u);
        atomicAdd(&g_deg[d.z], 1u);
        atomicAdd(&g_deg[d.w], 1u);
    }
    if (blockIdx.x == 0 && threadIdx.x == 0)
        for (int e = nv << 2; e < E; e++) atomicAdd(&g_deg[dst[e]], 1u);
}

// Histogram of degrees into NBIN bins.
__global__ void k_dhist(int N) {
    int i = blockIdx.x * blockDim.x + threadIdx.x;
    if (i >= N) return;
    unsigned d = g_deg[i];
    atomicAdd(&g_bins[d < NBIN ? d : NBIN - 1], 1u);
}

// Exclusive scan of bins (single block).
__global__ void k_dscan() {
    __shared__ unsigned int s[NBIN];
    int t = threadIdx.x;
    unsigned v = g_bins[t];
    s[t] = v;
    __syncthreads();
    for (int off = 1; off < NBIN; off <<= 1) {
        unsigned x = (t >= off) ? s[t - off] : 0u;
        __syncthreads();
        s[t] += x;
        __syncthreads();
    }
    g_bincur[t] = s[t] - v;   // exclusive prefix
}

// Assign slots: nodes ordered by degree (order within a bin arbitrary).
__global__ void k_rank(int N) {
    int i = blockIdx.x * blockDim.x + threadIdx.x;
    if (i >= N) return;
    unsigned d = g_deg[i];
    unsigned r = atomicAdd(&g_bincur[d < NBIN ? d : NBIN - 1], 1u);
    g_rank[i] = r;
    g_nodeofslot[r] = i;
    g_degslot[r] = d;
    g_cur[r] = 0u;
}

// Initial states: node space input -> slot-space state, node-space sbyte.
__global__ void k_init2(const float* __restrict__ s0, int N) {
    int i = blockIdx.x * blockDim.x + threadIdx.x;
    if (i >= N) return;
    const float4* p = (const float4*)(s0 + (size_t)i * 8);
    int st = onehot_idx(p[0], p[1]);
    g_stA[g_rank[i]] = (unsigned char)st;
    g_sbA[i] = (unsigned char)(1u << st);
}

// Scatter edges into slot-space ELL (entries = original src node ids).
__global__ void k_scatter(const int* __restrict__ src, const int* __restrict__ dst, int E) {
    int tid = blockIdx.x * blockDim.x + threadIdx.x;
    int stride = gridDim.x * blockDim.x;
    int nv = E >> 2;
    const int4* s4p = (const int4*)src;
    const int4* d4p = (const int4*)dst;
    for (int v = tid; v < nv; v += stride) {
        int4 s = __ldg(&s4p[v]);
        int4 d = __ldg(&d4p[v]);
        unsigned r0 = g_rank[d.x], r1 = g_rank[d.y], r2 = g_rank[d.z], r3 = g_rank[d.w];
        unsigned j0 = atomicAdd(&g_cur[r0], 1u);
        unsigned j1 = atomicAdd(&g_cur[r1], 1u);
        unsigned j2 = atomicAdd(&g_cur[r2], 1u);
        unsigned j3 = atomicAdd(&g_cur[r3], 1u);
        if (j0 < ELLW) g_ell[(size_t)j0 * MAXN + r0] = s.x;
        if (j1 < ELLW) g_ell[(size_t)j1 * MAXN + r1] = s.y;
        if (j2 < ELLW) g_ell[(size_t)j2 * MAXN + r2] = s.z;
        if (j3 < ELLW) g_ell[(size_t)j3 * MAXN + r3] = s.w;
    }
    if (blockIdx.x == 0 && threadIdx.x == 0) {
        for (int e = nv << 2; e < E; e++) {
            unsigned r = g_rank[dst[e]];
            unsigned j = atomicAdd(&g_cur[r], 1u);
            if (j < ELLW) g_ell[(size_t)j * MAXN + r] = src[e];
        }
    }
}

// Pad each slot's column to a multiple of 4 with the sentinel node (sbyte 0).
__global__ void k_pad(int N) {
    int i = blockIdx.x * blockDim.x + threadIdx.x;
    if (i >= N) return;
    unsigned d = g_degslot[i];
    unsigned dr = (d + 3u) & ~3u;
    for (unsigned j = d; j < dr && j < ELLW; j++)
        g_ell[(size_t)j * MAXN + i] = MAXN;   // sentinel
}

// One iteration. Warp gw handles slots [gw*32, gw*32+32); warps are assigned
// round-robin across blocks so each block samples all degree classes.
__global__ void k_iter(int flip, int N) {
    extern __shared__ unsigned char ss[];     // MAXN+16 sbyte bytes (node space)
    __shared__ unsigned char tbl[256 * NST];

    const unsigned char* sbin = flip ? g_sbB : g_sbA;
    unsigned char*       sbout = flip ? g_sbA : g_sbB;
    const unsigned char* stin  = flip ? g_stB : g_stA;
    unsigned char*       stout = flip ? g_stA : g_stB;

    // stage node-space sbyte array (+ zero the sentinel word region)
    int nv16 = (MAXN + 16) >> 4;
    const uint4* sv = (const uint4*)sbin;
    uint4* dv = (uint4*)ss;
    for (int i = threadIdx.x; i < nv16; i += blockDim.x) {
        uint4 x = sv[i];
        if (i == (MAXN >> 4)) { x = make_uint4(0, 0, 0, 0); }  // MAXN%16==0: sentinel block
        dv[i] = x;
    }
    for (int i = threadIdx.x; i < 256 * NST; i += blockDim.x) tbl[i] = g_table[i];
    __syncthreads();

    int lane = threadIdx.x & 31;
    int w = threadIdx.x >> 5;
    int gw = w * gridDim.x + blockIdx.x;     // round-robin warp->block
    int slot = gw * 32 + lane;
    if (slot >= N) return;

    unsigned d = g_degslot[slot];
    unsigned trips = (d + 3u) >> 2;
    const int* col = g_ell + slot;
    unsigned m = 0u;
    for (unsigned t = 0; t < trips; t++) {
        int i0 = __ldg(col);
        int i1 = __ldg(col + MAXN);
        int i2 = __ldg(col + 2 * MAXN);
        int i3 = __ldg(col + 3 * MAXN);
        col += 4 * MAXN;
        m |= (unsigned)ss[i0] | (unsigned)ss[i1] | (unsigned)ss[i2] | (unsigned)ss[i3];
    }

    unsigned s = stin[slot];
    unsigned char ns = tbl[(m << 3) | s];
    stout[slot] = ns;                                  // coalesced
    sbout[g_nodeofslot[slot]] = (unsigned char)(1u << ns);  // 1 random byte
}

__global__ void k_out(float* __restrict__ out, int N) {
    int i = blockIdx.x * blockDim.x + threadIdx.x;
    if (i >= N) return;
    int st = g_stA[i];                 // slot space
    int node = g_nodeofslot[i];
    float4 a, b;
    a.x = (st == 0) ? 1.0f : 0.0f;
    a.y = (st == 1) ? 1.0f : 0.0f;
    a.z = (st == 2) ? 1.0f : 0.0f;
    a.w = (st == 3) ? 1.0f : 0.0f;
    b.x = (st == 4) ? 1.0f : 0.0f;
    b.y = (st == 5) ? 1.0f : 0.0f;
    b.z = (st == 6) ? 1.0f : 0.0f;
    b.w = (st == 7) ? 1.0f : 0.0f;
    float4* o = (float4*)(out + (size_t)node * 8);
    o[0] = a;
    o[1] = b;
}

extern "C" void kernel_launch(void* const* d_in, const int* in_sizes, int n_in,
                              void* d_out, int out_size) {
    const float* s0 = (const float*)d_in[0];
    const int*   ei = (const int*)d_in[1];
    const float* T  = (const float*)d_in[2];

    int N = in_sizes[0] / 8;   // 100000
    int E = in_sizes[1] / 2;   // 6400000
    const int* src = ei;
    const int* dst = ei + E;

    int dev = 0, sms = 148;
    cudaGetDevice(&dev);
    cudaDeviceGetAttribute(&sms, cudaDevAttrMultiProcessorCount, dev);

    int smem_iter = ((MAXN + 16 + 15) & ~15);
    cudaFuncSetAttribute(k_iter, cudaFuncAttributeMaxDynamicSharedMemorySize, smem_iter);

    const int TB = 256;
    int nbN = (N + TB - 1) / TB;

    k_zero<<<nbN, TB>>>(N);
    k_table<<<(256 * NST + TB - 1) / TB, TB>>>(T);
    k_hist<<<sms * 4, TB>>>(dst, E);
    k_dhist<<<nbN, TB>>>(N);
    k_dscan<<<1, NBIN>>>();
    k_rank<<<nbN, TB>>>(N);
    k_init2<<<nbN, TB>>>(s0, N);
    k_scatter<<<sms * 4, TB>>>(src, dst, E);
    k_pad<<<nbN, TB>>>(N);

    const int ITB = 704;   // 22 warps; 148*22*32 = 104192 >= N
    for (int it = 0; it < 20; it++)
        k_iter<<<sms, ITB, smem_iter>>>(it & 1, N);

    k_out<<<nbN, TB>>>((float*)d_out, N);
}

// round 6
// speedup vs baseline: 1.2614x; 1.2614x over previous
#include <cuda_runtime.h>

// NeuralFSM == discrete automaton (exact):
//   state[n] in {0..7}; per iter mask[n] = OR of (1<<state[j]) over in-neighbors;
//   state'[n] = table[mask[n]][state[n]].
// Round 6 (from round-4 base): ELL interleaved in groups of 4 so each thread
// reads 4 neighbor ids with one int4 LDG.128; single sbyte array carries the
// state (s = ffs(sbyte)-1); sentinel-padded branch-free inner loop; grid covers
// all SMs. No degree sorting (round-5 lesson: preprocessing cost > benefit).

#define MAXN 100000
#define NST  8
#define ELLW 192   // max in-degree bound; Poisson(64) max ~110

__device__ __align__(16) unsigned char g_sbA[MAXN + 16];  // 1 << state
__device__ __align__(16) unsigned char g_sbB[MAXN + 16];
__device__ unsigned char g_table[256 * NST];
__device__ unsigned int  g_cnt[MAXN];                     // in-degree / cursor
// interleaved ELL: entry j of node n at g_ell[(j>>2)*(4*MAXN) + n*4 + (j&3)]
__device__ int           g_ell[(size_t)ELLW * MAXN];

static __device__ __forceinline__ int onehot_idx(float4 a, float4 b) {
    int st = 0;
    if (a.y > 0.5f) st = 1;
    if (a.z > 0.5f) st = 2;
    if (a.w > 0.5f) st = 3;
    if (b.x > 0.5f) st = 4;
    if (b.y > 0.5f) st = 5;
    if (b.z > 0.5f) st = 6;
    if (b.w > 0.5f) st = 7;
    return st;
}

__global__ void k_init(const float* __restrict__ s0, int n) {
    int i = blockIdx.x * blockDim.x + threadIdx.x;
    if (i >= n) return;
    const float4* p = (const float4*)(s0 + (size_t)i * 8);
    g_sbA[i] = (unsigned char)(1u << onehot_idx(p[0], p[1]));
    g_cnt[i] = 0u;
}

__global__ void k_table(const float* __restrict__ T) {
    int i = blockIdx.x * blockDim.x + threadIdx.x;
    if (i >= 256 * NST) return;
    const float4* p = (const float4*)(T + (size_t)i * 8);
    g_table[i] = (unsigned char)onehot_idx(p[0], p[1]);
}

static __device__ __forceinline__ void put_ell(int d, unsigned j, int s) {
    if (j < ELLW)
        g_ell[(size_t)(j >> 2) * (4 * MAXN) + (size_t)d * 4 + (j & 3)] = s;
}

__global__ void k_scatter(const int* __restrict__ src, const int* __restrict__ dst, int E) {
    int tid = blockIdx.x * blockDim.x + threadIdx.x;
    int stride = gridDim.x * blockDim.x;
    int nv = E >> 2;
    const int4* s4p = (const int4*)src;
    const int4* d4p = (const int4*)dst;
    for (int v = tid; v < nv; v += stride) {
        int4 s = __ldg(&s4p[v]);
        int4 d = __ldg(&d4p[v]);
        put_ell(d.x, atomicAdd(&g_cnt[d.x], 1u), s.x);
        put_ell(d.y, atomicAdd(&g_cnt[d.y], 1u), s.y);
        put_ell(d.z, atomicAdd(&g_cnt[d.z], 1u), s.z);
        put_ell(d.w, atomicAdd(&g_cnt[d.w], 1u), s.w);
    }
    if (blockIdx.x == 0 && threadIdx.x == 0)
        for (int e = nv << 2; e < E; e++)
            put_ell(dst[e], atomicAdd(&g_cnt[dst[e]], 1u), src[e]);
}

// Pad each node's list to a multiple of 4 with the sentinel (sbyte 0).
__global__ void k_pad(int N) {
    int i = blockIdx.x * blockDim.x + threadIdx.x;
    if (i >= N) return;
    unsigned d = g_cnt[i];
    unsigned dr = (d + 3u) & ~3u;
    for (unsigned j = d; j < dr; j++) put_ell(i, j, MAXN);
}

// One iteration: thread per node, int4 neighbor loads, smem byte gathers.
__global__ void k_iter(int flip, int N) {
    extern __shared__ unsigned char ss[];          // MAXN+16 sbyte bytes
    __shared__ unsigned char tbl[256 * NST];

    const unsigned char* sbin  = flip ? g_sbB : g_sbA;
    unsigned char*       sbout = flip ? g_sbA : g_sbB;

    // stage sbyte array + zeroed sentinel block (MAXN % 16 == 0)
    const int NV = MAXN >> 4;                      // 6250
    const uint4* sv = (const uint4*)sbin;
    uint4* dv = (uint4*)ss;
    for (int i = threadIdx.x; i <= NV; i += blockDim.x)
        dv[i] = (i < NV) ? sv[i] : make_uint4(0, 0, 0, 0);
    for (int i = threadIdx.x; i < 256 * NST; i += blockDim.x) tbl[i] = g_table[i];
    __syncthreads();

    int n = blockIdx.x * blockDim.x + threadIdx.x;
    if (n >= N) return;

    unsigned deg = g_cnt[n];
    unsigned trips = (deg + 3u) >> 2;              // int4 groups (padded)
    if (trips > ELLW / 4) trips = ELLW / 4;
    const int4* col = (const int4*)g_ell + n;      // group stride = MAXN int4s

    unsigned m = 0u;
    unsigned t = 0;
    for (; t + 2 <= trips; t += 2) {               // 8 edges in flight
        int4 v0 = __ldg(col + (size_t)t * MAXN);
        int4 v1 = __ldg(col + (size_t)(t + 1) * MAXN);
        m |= (unsigned)ss[v0.x] | (unsigned)ss[v0.y] | (unsigned)ss[v0.z] | (unsigned)ss[v0.w];
        m |= (unsigned)ss[v1.x] | (unsigned)ss[v1.y] | (unsigned)ss[v1.z] | (unsigned)ss[v1.w];
    }
    for (; t < trips; t++) {
        int4 v = __ldg(col + (size_t)t * MAXN);
        m |= (unsigned)ss[v.x] | (unsigned)ss[v.y] | (unsigned)ss[v.z] | (unsigned)ss[v.w];
    }

    unsigned s = (unsigned)__ffs((int)(unsigned)ss[n]) - 1u;
    unsigned char ns = tbl[(m << 3) | s];
    sbout[n] = (unsigned char)(1u << ns);
}

__global__ void k_out(float* __restrict__ out, int n) {
    int i = blockIdx.x * blockDim.x + threadIdx.x;
    if (i >= n) return;
    int st = __ffs((int)(unsigned)g_sbA[i]) - 1;
    float4 a, b;
    a.x = (st == 0) ? 1.0f : 0.0f;
    a.y = (st == 1) ? 1.0f : 0.0f;
    a.z = (st == 2) ? 1.0f : 0.0f;
    a.w = (st == 3) ? 1.0f : 0.0f;
    b.x = (st == 4) ? 1.0f : 0.0f;
    b.y = (st == 5) ? 1.0f : 0.0f;
    b.z = (st == 6) ? 1.0f : 0.0f;
    b.w = (st == 7) ? 1.0f : 0.0f;
    float4* o = (float4*)(out + (size_t)i * 8);
    o[0] = a;
    o[1] = b;
}

extern "C" void kernel_launch(void* const* d_in, const int* in_sizes, int n_in,
                              void* d_out, int out_size) {
    const float* s0 = (const float*)d_in[0];
    const int*   ei = (const int*)d_in[1];
    const float* T  = (const float*)d_in[2];

    int N = in_sizes[0] / 8;   // 100000
    int E = in_sizes[1] / 2;   // 6400000
    const int* src = ei;
    const int* dst = ei + E;

    int dev = 0, sms = 148;
    cudaGetDevice(&dev);
    cudaDeviceGetAttribute(&sms, cudaDevAttrMultiProcessorCount, dev);

    int smem_iter = MAXN + 16;
    cudaFuncSetAttribute(k_iter, cudaFuncAttributeMaxDynamicSharedMemorySize, smem_iter);

    const int TB = 256;
    int nbN = (N + TB - 1) / TB;

    k_init<<<nbN, TB>>>(s0, N);
    k_table<<<(256 * NST + TB - 1) / TB, TB>>>(T);
    k_scatter<<<sms * 4, TB>>>(src, dst, E);
    k_pad<<<nbN, TB>>>(N);

    // spread nodes across all SMs: one block per SM, warp-rounded block size
    int itb = ((N + sms - 1) / sms + 31) & ~31;    // 704 for N=100000, sms=148
    if (itb > 1024) itb = 1024;
    int nbI = (N + itb - 1) / itb;
    for (int it = 0; it < 20; it++)
        k_iter<<<nbI, itb, smem_iter>>>(it & 1, N);

    k_out<<<nbN, TB>>>((float*)d_out, N);
}

// round 7
// speedup vs baseline: 1.5132x; 1.1996x over previous
#include <cuda_runtime.h>
#include <cstdint>

// NeuralFSM == discrete automaton (exact):
//   state[n] in {0..7}; per iter mask[n] = OR of (1<<state[j]) over in-neighbors;
//   state'[n] = table[mask[n]][state[n]].
// Round 7 (from round-6 base): early saturation break (m==255 is the hard max,
// exact), 4-deep int4 load pipeline, cp.async.bulk staging of the sbyte array,
// merged boot kernel. ELL interleaved in groups of 4 (one int4 = 4 neighbors).

#define MAXN 100000
#define NST  8
#define ELLW 192   // max in-degree bound; Poisson(64) max ~110

__device__ __align__(16) unsigned char g_sbA[MAXN + 16];  // 1 << state
__device__ __align__(16) unsigned char g_sbB[MAXN + 16];
__device__ unsigned char g_table[256 * NST];
__device__ unsigned int  g_cnt[MAXN];                     // in-degree / cursor
// interleaved ELL: entry j of node n at g_ell[(j>>2)*(4*MAXN) + n*4 + (j&3)]
__device__ int           g_ell[(size_t)ELLW * MAXN];

static __device__ __forceinline__ int onehot_idx(float4 a, float4 b) {
    int st = 0;
    if (a.y > 0.5f) st = 1;
    if (a.z > 0.5f) st = 2;
    if (a.w > 0.5f) st = 3;
    if (b.x > 0.5f) st = 4;
    if (b.y > 0.5f) st = 5;
    if (b.z > 0.5f) st = 6;
    if (b.w > 0.5f) st = 7;
    return st;
}

// init states + counters + transition table in one launch
__global__ void k_boot(const float* __restrict__ s0, const float* __restrict__ T, int N) {
    int i = blockIdx.x * blockDim.x + threadIdx.x;
    if (i < N) {
        const float4* p = (const float4*)(s0 + (size_t)i * 8);
        g_sbA[i] = (unsigned char)(1u << onehot_idx(p[0], p[1]));
        g_cnt[i] = 0u;
    }
    if (i < 256 * NST) {
        const float4* p = (const float4*)(T + (size_t)i * 8);
        g_table[i] = (unsigned char)onehot_idx(p[0], p[1]);
    }
}

static __device__ __forceinline__ void put_ell(int d, unsigned j, int s) {
    if (j < ELLW)
        g_ell[(size_t)(j >> 2) * (4 * MAXN) + (size_t)d * 4 + (j & 3)] = s;
}

__global__ void k_scatter(const int* __restrict__ src, const int* __restrict__ dst, int E) {
    int tid = blockIdx.x * blockDim.x + threadIdx.x;
    int stride = gridDim.x * blockDim.x;
    int nv = E >> 2;
    const int4* s4p = (const int4*)src;
    const int4* d4p = (const int4*)dst;
    for (int v = tid; v < nv; v += stride) {
        int4 s = __ldg(&s4p[v]);
        int4 d = __ldg(&d4p[v]);
        put_ell(d.x, atomicAdd(&g_cnt[d.x], 1u), s.x);
        put_ell(d.y, atomicAdd(&g_cnt[d.y], 1u), s.y);
        put_ell(d.z, atomicAdd(&g_cnt[d.z], 1u), s.z);
        put_ell(d.w, atomicAdd(&g_cnt[d.w], 1u), s.w);
    }
    if (blockIdx.x == 0 && threadIdx.x == 0)
        for (int e = nv << 2; e < E; e++)
            put_ell(dst[e], atomicAdd(&g_cnt[dst[e]], 1u), src[e]);
}

// Pad each node's list to a multiple of 4 with the sentinel (sbyte 0).
__global__ void k_pad(int N) {
    int i = blockIdx.x * blockDim.x + threadIdx.x;
    if (i >= N) return;
    unsigned d = g_cnt[i];
    unsigned dr = (d + 3u) & ~3u;
    for (unsigned j = d; j < dr; j++) put_ell(i, j, MAXN);
}

// One iteration: thread per node, 4-deep int4 pipeline, smem byte gathers,
// early break once the mask saturates at 255 (hard maximum -> exact).
__global__ void k_iter(int flip, int N) {
    extern __shared__ __align__(16) unsigned char ss[];   // MAXN+16 sbyte bytes
    __shared__ unsigned char tbl[256 * NST];
    __shared__ __align__(8) unsigned long long mbar;

    const unsigned char* sbin  = flip ? g_sbB : g_sbA;
    unsigned char*       sbout = flip ? g_sbA : g_sbB;

    // --- bulk-async stage of the sbyte array into shared memory ---
    uint32_t mbar_a;
    {
        uint64_t t64;
        asm("{ .reg .u64 x; cvta.to.shared.u64 x, %1; cvt.u32.u64 %0, x; }"
            : "=l"(t64) : "l"(&mbar));
        mbar_a = (uint32_t)t64;
    }
    uint32_t ss_a;
    {
        uint64_t t64;
        asm("{ .reg .u64 x; cvta.to.shared.u64 x, %1; cvt.u32.u64 %0, x; }"
            : "=l"(t64) : "l"(ss));
        ss_a = (uint32_t)t64;
    }
    if (threadIdx.x == 0) {
        asm volatile("mbarrier.init.shared.b64 [%0], 1;" :: "r"(mbar_a) : "memory");
        // zero sentinel block
        *(uint4*)(ss + MAXN) = make_uint4(0, 0, 0, 0);
    }
    __syncthreads();
    if (threadIdx.x == 0) {
        asm volatile("mbarrier.arrive.expect_tx.shared.b64 _, [%0], %1;"
                     :: "r"(mbar_a), "r"((unsigned)MAXN) : "memory");
        asm volatile("cp.async.bulk.shared::cta.global.mbarrier::complete_tx::bytes "
                     "[%0], [%1], %2, [%3];"
                     :: "r"(ss_a), "l"(sbin), "r"((unsigned)MAXN), "r"(mbar_a)
                     : "memory");
    }
    // table copy (2KB) with regular loads meanwhile
    for (int i = threadIdx.x; i < 256 * NST; i += blockDim.x) tbl[i] = g_table[i];
    // wait for bulk copy
    {
        unsigned done;
        asm volatile(
            "{\n\t.reg .pred p;\n\t"
            "mbarrier.try_wait.parity.acquire.cta.shared::cta.b64 p, [%1], 0;\n\t"
            "selp.b32 %0, 1, 0, p;\n\t}"
            : "=r"(done) : "r"(mbar_a) : "memory");
        while (!done) {
            asm volatile(
                "{\n\t.reg .pred p;\n\t"
                "mbarrier.try_wait.parity.acquire.cta.shared::cta.b64 p, [%1], 0, 0x989680;\n\t"
                "selp.b32 %0, 1, 0, p;\n\t}"
                : "=r"(done) : "r"(mbar_a) : "memory");
        }
    }
    __syncthreads();

    int n = blockIdx.x * blockDim.x + threadIdx.x;
    if (n >= N) return;

    unsigned deg = g_cnt[n];
    unsigned trips = (deg + 3u) >> 2;              // int4 groups (padded)
    if (trips > ELLW / 4) trips = ELLW / 4;
    const int4* col = (const int4*)g_ell + n;      // group stride = MAXN int4s

    unsigned m = 0u;
    unsigned t = 0;
    // 4 int4 loads (16 edges) in flight per chunk; early break at saturation
    for (; t + 4 <= trips; t += 4) {
        int4 v0 = __ldg(col + (size_t)(t + 0) * MAXN);
        int4 v1 = __ldg(col + (size_t)(t + 1) * MAXN);
        int4 v2 = __ldg(col + (size_t)(t + 2) * MAXN);
        int4 v3 = __ldg(col + (size_t)(t + 3) * MAXN);
        m |= (unsigned)ss[v0.x] | (unsigned)ss[v0.y] | (unsigned)ss[v0.z] | (unsigned)ss[v0.w];
        m |= (unsigned)ss[v1.x] | (unsigned)ss[v1.y] | (unsigned)ss[v1.z] | (unsigned)ss[v1.w];
        m |= (unsigned)ss[v2.x] | (unsigned)ss[v2.y] | (unsigned)ss[v2.z] | (unsigned)ss[v2.w];
        m |= (unsigned)ss[v3.x] | (unsigned)ss[v3.y] | (unsigned)ss[v3.z] | (unsigned)ss[v3.w];
        if (m == 255u) { t = trips; break; }       // hard max reached: exact
    }
    for (; t < trips; t++) {
        int4 v = __ldg(col + (size_t)t * MAXN);
        m |= (unsigned)ss[v.x] | (unsigned)ss[v.y] | (unsigned)ss[v.z] | (unsigned)ss[v.w];
        if (m == 255u) break;
    }

    unsigned s = (unsigned)__ffs((int)(unsigned)ss[n]) - 1u;
    unsigned char ns = tbl[(m << 3) | s];
    sbout[n] = (unsigned char)(1u << ns);
}

__global__ void k_out(float* __restrict__ out, int n) {
    int i = blockIdx.x * blockDim.x + threadIdx.x;
    if (i >= n) return;
    int st = __ffs((int)(unsigned)g_sbA[i]) - 1;
    float4 a, b;
    a.x = (st == 0) ? 1.0f : 0.0f;
    a.y = (st == 1) ? 1.0f : 0.0f;
    a.z = (st == 2) ? 1.0f : 0.0f;
    a.w = (st == 3) ? 1.0f : 0.0f;
    b.x = (st == 4) ? 1.0f : 0.0f;
    b.y = (st == 5) ? 1.0f : 0.0f;
    b.z = (st == 6) ? 1.0f : 0.0f;
    b.w = (st == 7) ? 1.0f : 0.0f;
    float4* o = (float4*)(out + (size_t)i * 8);
    o[0] = a;
    o[1] = b;
}

extern "C" void kernel_launch(void* const* d_in, const int* in_sizes, int n_in,
                              void* d_out, int out_size) {
    const float* s0 = (const float*)d_in[0];
    const int*   ei = (const int*)d_in[1];
    const float* T  = (const float*)d_in[2];

    int N = in_sizes[0] / 8;   // 100000
    int E = in_sizes[1] / 2;   // 6400000
    const int* src = ei;
    const int* dst = ei + E;

    int dev = 0, sms = 148;
    cudaGetDevice(&dev);
    cudaDeviceGetAttribute(&sms, cudaDevAttrMultiProcessorCount, dev);

    int smem_iter = MAXN + 16;
    cudaFuncSetAttribute(k_iter, cudaFuncAttributeMaxDynamicSharedMemorySize, smem_iter);

    const int TB = 256;
    int nbN = (N + TB - 1) / TB;

    k_boot<<<nbN, TB>>>(s0, T, N);
    k_scatter<<<sms * 4, TB>>>(src, dst, E);
    k_pad<<<nbN, TB>>>(N);

    // spread nodes across all SMs: one block per SM, warp-rounded block size
    int itb = ((N + sms - 1) / sms + 31) & ~31;    // 704 for N=100000, sms=148
    if (itb > 1024) itb = 1024;
    int nbI = (N + itb - 1) / itb;
    for (int it = 0; it < 20; it++)
        k_iter<<<nbI, itb, smem_iter>>>(it & 1, N);

    k_out<<<nbN, TB>>>((float*)d_out, N);
}

// round 8
// speedup vs baseline: 1.5248x; 1.0077x over previous
#include <cuda_runtime.h>
#include <cstdint>

// NeuralFSM == discrete automaton (exact):
//   state[n] in {0..7}; per iter mask[n] = OR of (1<<state[j]) over in-neighbors;
//   state'[n] = table[mask[n]][state[n]].
// Round 8: persistent iteration kernel (1 block/SM, co-residency forced by
// 100KB smem) with a monotone-counter grid barrier; pad folded in; per-iter
// cp.async.bulk restage; early saturation break (m==255, exact); interleaved
// int4 ELL.

#define MAXN 100000
#define NST  8
#define ELLW 192   // max in-degree bound; Poisson(64) max ~110
#define ITERS 20

__device__ __align__(16) unsigned char g_sbA[MAXN + 16];  // 1 << state
__device__ __align__(16) unsigned char g_sbB[MAXN + 16];
__device__ unsigned char g_table[256 * NST];
__device__ unsigned int  g_cnt[MAXN];                     // in-degree / cursor
__device__ unsigned int  g_bar;                           // grid barrier counter
// interleaved ELL: entry j of node n at g_ell[(j>>2)*(4*MAXN) + n*4 + (j&3)]
__device__ int           g_ell[(size_t)ELLW * MAXN];

static __device__ __forceinline__ int onehot_idx(float4 a, float4 b) {
    int st = 0;
    if (a.y > 0.5f) st = 1;
    if (a.z > 0.5f) st = 2;
    if (a.w > 0.5f) st = 3;
    if (b.x > 0.5f) st = 4;
    if (b.y > 0.5f) st = 5;
    if (b.z > 0.5f) st = 6;
    if (b.w > 0.5f) st = 7;
    return st;
}

__global__ void k_boot(const float* __restrict__ s0, const float* __restrict__ T, int N) {
    int i = blockIdx.x * blockDim.x + threadIdx.x;
    if (i == 0) g_bar = 0u;   // reset barrier for every graph replay
    if (i < N) {
        const float4* p = (const float4*)(s0 + (size_t)i * 8);
        g_sbA[i] = (unsigned char)(1u << onehot_idx(p[0], p[1]));
        g_cnt[i] = 0u;
    }
    if (i < 256 * NST) {
        const float4* p = (const float4*)(T + (size_t)i * 8);
        g_table[i] = (unsigned char)onehot_idx(p[0], p[1]);
    }
}

static __device__ __forceinline__ void put_ell(int d, unsigned j, int s) {
    if (j < ELLW)
        g_ell[(size_t)(j >> 2) * (4 * MAXN) + (size_t)d * 4 + (j & 3)] = s;
}

__global__ void k_scatter(const int* __restrict__ src, const int* __restrict__ dst, int E) {
    int tid = blockIdx.x * blockDim.x + threadIdx.x;
    int stride = gridDim.x * blockDim.x;
    int nv = E >> 2;
    const int4* s4p = (const int4*)src;
    const int4* d4p = (const int4*)dst;
    for (int v = tid; v < nv; v += stride) {
        int4 s = __ldg(&s4p[v]);
        int4 d = __ldg(&d4p[v]);
        put_ell(d.x, atomicAdd(&g_cnt[d.x], 1u), s.x);
        put_ell(d.y, atomicAdd(&g_cnt[d.y], 1u), s.y);
        put_ell(d.z, atomicAdd(&g_cnt[d.z], 1u), s.z);
        put_ell(d.w, atomicAdd(&g_cnt[d.w], 1u), s.w);
    }
    if (blockIdx.x == 0 && threadIdx.x == 0)
        for (int e = nv << 2; e < E; e++)
            put_ell(dst[e], atomicAdd(&g_cnt[dst[e]], 1u), src[e]);
}

static __device__ __forceinline__ uint32_t smem_addr32(const void* p) {
    uint64_t t64;
    asm("{ .reg .u64 x; cvta.to.shared.u64 x, %1; cvt.u32.u64 %0, x; }"
        : "=l"(t64) : "l"(p));
    return (uint32_t)t64;
}

// Monotone-counter grid barrier: all gridDim.x blocks arrive; spin to target.
static __device__ __forceinline__ void grid_barrier(unsigned target) {
    __syncthreads();
    if (threadIdx.x == 0) {
        __threadfence();
        atomicAdd(&g_bar, 1u);
        while (atomicAdd(&g_bar, 0u) < target) { }
    }
    __syncthreads();
}

// Persistent kernel: pad + 20 iterations, one grid barrier per iteration.
__global__ void __launch_bounds__(704, 1) k_persist(int N) {
    extern __shared__ __align__(16) unsigned char ss[];   // MAXN+16 bytes
    __shared__ unsigned char tbl[256 * NST];
    __shared__ __align__(8) unsigned long long mbar;

    const int nb = gridDim.x;

    // ---- prologue: pad ELL columns to a multiple of 4 with sentinel ----
    for (int i = blockIdx.x * blockDim.x + threadIdx.x; i < N; i += nb * blockDim.x) {
        unsigned d = g_cnt[i];
        unsigned dr = (d + 3u) & ~3u;
        for (unsigned j = d; j < dr; j++) put_ell(i, j, MAXN);
    }
    // table + sentinel + mbarrier init (once)
    for (int i = threadIdx.x; i < 256 * NST; i += blockDim.x) tbl[i] = g_table[i];
    uint32_t mbar_a = smem_addr32(&mbar);
    uint32_t ss_a = smem_addr32(ss);
    if (threadIdx.x == 0) {
        *(uint4*)(ss + MAXN) = make_uint4(0, 0, 0, 0);
        asm volatile("mbarrier.init.shared.b64 [%0], 1;" :: "r"(mbar_a) : "memory");
    }
    grid_barrier(nb);   // pad visible everywhere

    int n = blockIdx.x * blockDim.x + threadIdx.x;
    unsigned deg = (n < N) ? g_cnt[n] : 0u;
    unsigned trips = (deg + 3u) >> 2;
    if (trips > ELLW / 4) trips = ELLW / 4;
    const int4* col = (const int4*)g_ell + n;

    for (int it = 0; it < ITERS; it++) {
        const unsigned char* sbin  = (it & 1) ? g_sbB : g_sbA;
        unsigned char*       sbout = (it & 1) ? g_sbA : g_sbB;

        // bulk-async restage of sbyte array
        if (threadIdx.x == 0) {
            asm volatile("mbarrier.arrive.expect_tx.shared.b64 _, [%0], %1;"
                         :: "r"(mbar_a), "r"((unsigned)MAXN) : "memory");
            asm volatile("cp.async.bulk.shared::cta.global.mbarrier::complete_tx::bytes "
                         "[%0], [%1], %2, [%3];"
                         :: "r"(ss_a), "l"(sbin), "r"((unsigned)MAXN), "r"(mbar_a)
                         : "memory");
        }
        {
            unsigned done, par = (unsigned)(it & 1);
            do {
                asm volatile(
                    "{\n\t.reg .pred p;\n\t"
                    "mbarrier.try_wait.parity.acquire.cta.shared::cta.b64 p, [%1], %2, 0x989680;\n\t"
                    "selp.b32 %0, 1, 0, p;\n\t}"
                    : "=r"(done) : "r"(mbar_a), "r"(par) : "memory");
            } while (!done);
        }
        __syncthreads();

        if (n < N) {
            unsigned m = 0u;
            unsigned t = 0;
            for (; t + 4 <= trips; t += 4) {
                int4 v0 = __ldg(col + (size_t)(t + 0) * MAXN);
                int4 v1 = __ldg(col + (size_t)(t + 1) * MAXN);
                int4 v2 = __ldg(col + (size_t)(t + 2) * MAXN);
                int4 v3 = __ldg(col + (size_t)(t + 3) * MAXN);
                m |= (unsigned)ss[v0.x] | (unsigned)ss[v0.y] | (unsigned)ss[v0.z] | (unsigned)ss[v0.w];
                m |= (unsigned)ss[v1.x] | (unsigned)ss[v1.y] | (unsigned)ss[v1.z] | (unsigned)ss[v1.w];
                m |= (unsigned)ss[v2.x] | (unsigned)ss[v2.y] | (unsigned)ss[v2.z] | (unsigned)ss[v2.w];
                m |= (unsigned)ss[v3.x] | (unsigned)ss[v3.y] | (unsigned)ss[v3.z] | (unsigned)ss[v3.w];
                if (m == 255u) { t = trips; break; }   // hard max: exact
            }
            for (; t < trips; t++) {
                int4 v = __ldg(col + (size_t)t * MAXN);
                m |= (unsigned)ss[v.x] | (unsigned)ss[v.y] | (unsigned)ss[v.z] | (unsigned)ss[v.w];
                if (m == 255u) break;
            }
            unsigned s = (unsigned)__ffs((int)(unsigned)ss[n]) - 1u;
            sbout[n] = (unsigned char)(1u << tbl[(m << 3) | s]);
        }

        grid_barrier((unsigned)(nb * (it + 2)));   // writes visible before restage
    }
}

__global__ void k_out(float* __restrict__ out, int n) {
    int i = blockIdx.x * blockDim.x + threadIdx.x;
    if (i >= n) return;
    int st = __ffs((int)(unsigned)g_sbA[i]) - 1;
    float4 a, b;
    a.x = (st == 0) ? 1.0f : 0.0f;
    a.y = (st == 1) ? 1.0f : 0.0f;
    a.z = (st == 2) ? 1.0f : 0.0f;
    a.w = (st == 3) ? 1.0f : 0.0f;
    b.x = (st == 4) ? 1.0f : 0.0f;
    b.y = (st == 5) ? 1.0f : 0.0f;
    b.z = (st == 6) ? 1.0f : 0.0f;
    b.w = (st == 7) ? 1.0f : 0.0f;
    float4* o = (float4*)(out + (size_t)i * 8);
    o[0] = a;
    o[1] = b;
}

extern "C" void kernel_launch(void* const* d_in, const int* in_sizes, int n_in,
                              void* d_out, int out_size) {
    const float* s0 = (const float*)d_in[0];
    const int*   ei = (const int*)d_in[1];
    const float* T  = (const float*)d_in[2];

    int N = in_sizes[0] / 8;   // 100000
    int E = in_sizes[1] / 2;   // 6400000
    const int* src = ei;
    const int* dst = ei + E;

    int dev = 0, sms = 148;
    cudaGetDevice(&dev);
    cudaDeviceGetAttribute(&sms, cudaDevAttrMultiProcessorCount, dev);

    int smem_iter = MAXN + 16;
    cudaFuncSetAttribute(k_persist, cudaFuncAttributeMaxDynamicSharedMemorySize, smem_iter);

    const int TB = 256;
    int nbN = (N + TB - 1) / TB;

    k_boot<<<nbN, TB>>>(s0, T, N);
    k_scatter<<<sms * 4, TB>>>(src, dst, E);

    // 704 threads/block, sms blocks: thread-per-node covers N (148*704=104192),
    // 100KB smem forces 1 block/SM -> all blocks co-resident (spin barrier safe).
    k_persist<<<sms, 704, smem_iter>>>(N);

    k_out<<<nbN, TB>>>((float*)d_out, N);
}